// round 12
// baseline (speedup 1.0000x reference)
#include <cuda_runtime.h>
#include <math.h>

#define Nn 50000
#define Ee 1600000
#define IND 256
#define Hd 64
#define Cc 16
#define Ll 2
#define NTr 5000

#define SCAN_B 1024
#define NBLK ((Nn + SCAN_B - 1) / SCAN_B)   // 49

// ---------------- device scratch (no allocations allowed) ----------------
__device__ __align__(16) float g_x[Nn * Hd];
__device__ __align__(16) float g_h[Nn * Hd];
__device__ float g_dinv[Nn];
__device__ int   g_deg[Nn];
__device__ int   g_off[Nn + 1];
__device__ int   g_cur[Nn];
__device__ int   g_csrsrc[Ee];
__device__ int   g_bsum[NBLK];

// ---------------- CSR build ----------------
__global__ void k_count(const int* __restrict__ dst) {
    int e = blockIdx.x * blockDim.x + threadIdx.x;
    if (e < Ee) atomicAdd(&g_deg[dst[e]], 1);
}

__global__ void k_scan1() {
    __shared__ int warpsums[32];
    int tid = threadIdx.x;
    int lane = tid & 31, wid = tid >> 5;
    int i = blockIdx.x * SCAN_B + tid;
    int v = (i < Nn) ? g_deg[i] : 0;
    if (i < Nn) g_dinv[i] = rsqrtf((float)v + 1.0f);   // +1 self loop

    int x = v;
#pragma unroll
    for (int d = 1; d < 32; d <<= 1) {
        int t = __shfl_up_sync(0xffffffffu, x, d);
        if (lane >= d) x += t;
    }
    if (lane == 31) warpsums[wid] = x;
    __syncthreads();
    if (wid == 0) {
        int w = warpsums[lane];
#pragma unroll
        for (int d = 1; d < 32; d <<= 1) {
            int t = __shfl_up_sync(0xffffffffu, w, d);
            if (lane >= d) w += t;
        }
        warpsums[lane] = w;
    }
    __syncthreads();
    int excl = x - v + (wid ? warpsums[wid - 1] : 0);
    if (i < Nn) g_off[i] = excl;
    if (tid == SCAN_B - 1) g_bsum[blockIdx.x] = excl + v;
}

__global__ void k_scan2() {
    __shared__ int s[64];
    int tid = threadIdx.x;    // blockDim = 64
    int v = (tid < NBLK) ? g_bsum[tid] : 0;
    s[tid] = v;
    __syncthreads();
#pragma unroll
    for (int d = 1; d < 64; d <<= 1) {
        int t = (tid >= d) ? s[tid - d] : 0;
        __syncthreads();
        s[tid] += t;
        __syncthreads();
    }
    if (tid < NBLK) g_bsum[tid] = s[tid] - v;
    if (tid == NBLK - 1) g_off[Nn] = s[tid];
}

__global__ void k_scan3() {
    int i = blockIdx.x * SCAN_B + threadIdx.x;
    if (i < Nn) {
        int o = g_off[i] + g_bsum[blockIdx.x];
        g_off[i] = o;
        g_cur[i] = o;
    }
}

__global__ void k_fill(const int* __restrict__ el) {
    int e = blockIdx.x * blockDim.x + threadIdx.x;
    if (e < Ee) {
        int s = el[e];
        int d = el[Ee + e];
        int p = atomicAdd(&g_cur[d], 1);
        g_csrsrc[p] = s;
    }
}

// ---------------- GEMM: A[N,K] @ W[K,64] -> Out[N,64] (R5 proven version) ----------------
__global__ void k_gemm64(const float* __restrict__ A, const float* __restrict__ W,
                         float* __restrict__ Out, int K) {
    __shared__ float As[64 * 65];
    __shared__ float Ws[64 * 64];
    int tid = threadIdx.x;
    int rq = tid >> 4;
    int cq = tid & 15;
    int row0 = blockIdx.x * 64;
    float acc[4][4];
#pragma unroll
    for (int i = 0; i < 4; i++)
#pragma unroll
        for (int j = 0; j < 4; j++) acc[i][j] = 0.f;

    for (int kt = 0; kt < K; kt += 64) {
#pragma unroll
        for (int q = 0; q < 16; q++) {
            int pos = tid + 256 * q;
            int ar = pos >> 6, ac = pos & 63;
            int grow = row0 + ar;
            As[ar * 65 + ac] = (grow < Nn) ? A[(size_t)grow * K + kt + ac] : 0.f;
            Ws[pos] = W[(size_t)(kt + ar) * 64 + ac];
        }
        __syncthreads();
#pragma unroll
        for (int k = 0; k < 64; k++) {
            float a0 = As[(rq * 4 + 0) * 65 + k];
            float a1 = As[(rq * 4 + 1) * 65 + k];
            float a2 = As[(rq * 4 + 2) * 65 + k];
            float a3 = As[(rq * 4 + 3) * 65 + k];
            float4 w = *(const float4*)(&Ws[k * 64 + cq * 4]);
            acc[0][0] += a0 * w.x; acc[0][1] += a0 * w.y; acc[0][2] += a0 * w.z; acc[0][3] += a0 * w.w;
            acc[1][0] += a1 * w.x; acc[1][1] += a1 * w.y; acc[1][2] += a1 * w.z; acc[1][3] += a1 * w.w;
            acc[2][0] += a2 * w.x; acc[2][1] += a2 * w.y; acc[2][2] += a2 * w.z; acc[2][3] += a2 * w.w;
            acc[3][0] += a3 * w.x; acc[3][1] += a3 * w.y; acc[3][2] += a3 * w.z; acc[3][3] += a3 * w.w;
        }
        __syncthreads();
    }
#pragma unroll
    for (int i = 0; i < 4; i++) {
        int grow = row0 + rq * 4 + i;
        if (grow < Nn) {
            float4 v = make_float4(acc[i][0], acc[i][1], acc[i][2], acc[i][3]);
            *(float4*)(&Out[(size_t)grow * 64 + cq * 4]) = v;
        }
    }
}

// ---------------- aggregation (warp per node, float2 lanes, x4 unroll) ----------------
// lane handles feature columns (2*lane, 2*lane+1); one LDG.64 per neighbor.
__global__ void k_aggregate(const float2* __restrict__ x2, float2* __restrict__ out2,
                            const float2* __restrict__ bias2, int dorelu) {
    int warp = (blockIdx.x * blockDim.x + threadIdx.x) >> 5;
    int lane = threadIdx.x & 31;
    if (warp >= Nn) return;
    float di = g_dinv[warp];
    float sn = di * di;
    float2 xv = x2[(size_t)warp * 32 + lane];
    float acc0 = sn * xv.x;
    float acc1 = sn * xv.y;
    int p = g_off[warp], end = g_off[warp + 1];

    for (; p + 4 <= end; p += 4) {
        int s0 = g_csrsrc[p + 0];
        int s1 = g_csrsrc[p + 1];
        int s2 = g_csrsrc[p + 2];
        int s3 = g_csrsrc[p + 3];
        float2 v0 = x2[(size_t)s0 * 32 + lane];
        float2 v1 = x2[(size_t)s1 * 32 + lane];
        float2 v2 = x2[(size_t)s2 * 32 + lane];
        float2 v3 = x2[(size_t)s3 * 32 + lane];
        float n0 = di * g_dinv[s0];
        float n1 = di * g_dinv[s1];
        float n2 = di * g_dinv[s2];
        float n3 = di * g_dinv[s3];
        acc0 += n0 * v0.x; acc1 += n0 * v0.y;
        acc0 += n1 * v1.x; acc1 += n1 * v1.y;
        acc0 += n2 * v2.x; acc1 += n2 * v2.y;
        acc0 += n3 * v3.x; acc1 += n3 * v3.y;
    }
    for (; p < end; p++) {
        int s = g_csrsrc[p];
        float2 v = x2[(size_t)s * 32 + lane];
        float nrm = di * g_dinv[s];
        acc0 += nrm * v.x;
        acc1 += nrm * v.y;
    }
    float2 b = bias2[lane];
    acc0 += b.x;
    acc1 += b.y;
    if (dorelu) { acc0 = fmaxf(acc0, 0.f); acc1 = fmaxf(acc1, 0.f); }
    out2[(size_t)warp * 32 + lane] = make_float2(acc0, acc1);
}

// ---------------- row L2 normalize (warp per node, float2) ----------------
__global__ void k_norm(float2* __restrict__ h2, float* __restrict__ hout) {
    int warp = (blockIdx.x * blockDim.x + threadIdx.x) >> 5;
    int lane = threadIdx.x & 31;
    if (warp >= Nn) return;
    float2 v = h2[(size_t)warp * 32 + lane];
    float ss = v.x * v.x + v.y * v.y;
#pragma unroll
    for (int d = 16; d; d >>= 1) ss += __shfl_xor_sync(0xffffffff, ss, d);
    float inv = 1.f / fmaxf(sqrtf(ss), 1e-12f);
    v.x *= inv; v.y *= inv;
    h2[(size_t)warp * 32 + lane] = v;
    // hout only 4B-aligned: scalar but coalesced-pair stores
    hout[(size_t)warp * 64 + 2 * lane + 0] = v.x;
    hout[(size_t)warp * 64 + 2 * lane + 1] = v.y;
}

// ---------------- head: logits = h@W3 + b3 ; log_softmax ----------------
__global__ void k_head(const float* __restrict__ h, const float* __restrict__ W3,
                       const float* __restrict__ b3, float* __restrict__ pred) {
    __shared__ float Ws[64 * 16];
    __shared__ float bs[16];
    int tid = threadIdx.x;
    for (int i = tid; i < 64 * 16; i += 256) Ws[i] = W3[i];
    if (tid < 16) bs[tid] = b3[tid];
    __syncthreads();
    int n = blockIdx.x * 256 + tid;
    if (n >= Nn) return;
    float hv[64];
#pragma unroll
    for (int q = 0; q < 16; q++) {
        float4 v = *(const float4*)(&h[(size_t)n * 64 + q * 4]);
        hv[q * 4 + 0] = v.x; hv[q * 4 + 1] = v.y; hv[q * 4 + 2] = v.z; hv[q * 4 + 3] = v.w;
    }
    float lg[16];
#pragma unroll
    for (int c = 0; c < 16; c++) {
        float acc = bs[c];
#pragma unroll
        for (int k = 0; k < 64; k++) acc += hv[k] * Ws[k * 16 + c];
        lg[c] = acc;
    }
    float m = lg[0];
#pragma unroll
    for (int c = 1; c < 16; c++) m = fmaxf(m, lg[c]);
    float s = 0.f;
#pragma unroll
    for (int c = 0; c < 16; c++) s += __expf(lg[c] - m);
    float lse = m + __logf(s);
#pragma unroll
    for (int c = 0; c < 16; c++) pred[(size_t)n * 16 + c] = lg[c] - lse;
}

// ---------------- nll loss ----------------
__global__ void k_loss(const float* __restrict__ pred, const int* __restrict__ labels,
                       const int* __restrict__ tidx, float* __restrict__ out0) {
    __shared__ float s[1024];
    int t = threadIdx.x;
    float local = 0.f;
    for (int i = t; i < NTr; i += 1024) {
        int n = tidx[i];
        int lbl = labels[n];
        local += pred[(size_t)n * 16 + lbl];
    }
    s[t] = local;
    __syncthreads();
    for (int d = 512; d > 0; d >>= 1) {
        if (t < d) s[t] += s[t + d];
        __syncthreads();
    }
    if (t == 0) out0[0] = -s[0] / (float)NTr;
}

// ---------------- launch: fork CSR build alongside GEMM1, join at aggregate ----------------
extern "C" void kernel_launch(void* const* d_in, const int* in_sizes, int n_in,
                              void* d_out, int out_size) {
    const float* feats  = (const float*)d_in[0];
    const float* W1     = (const float*)d_in[1];
    const float* b1     = (const float*)d_in[2];
    const float* W2     = (const float*)d_in[3];
    const float* b2     = (const float*)d_in[4];
    const float* W3     = (const float*)d_in[5];
    const float* b3     = (const float*)d_in[6];
    const int*   el     = (const int*)d_in[7];
    const int*   labels = (const int*)d_in[8];
    const int*   tidx   = (const int*)d_in[9];
    float* out  = (float*)d_out;
    float* pred = out + 1;
    float* hout = out + 1 + (size_t)Nn * Cc;

    void *px, *ph, *pdeg;
    cudaGetSymbolAddress(&px, g_x);
    cudaGetSymbolAddress(&ph, g_h);
    cudaGetSymbolAddress(&pdeg, g_deg);
    float* x = (float*)px;
    float* h = (float*)ph;
    float2* x2 = (float2*)px;
    float2* h2 = (float2*)ph;

    // host-side stream/event objects, created once and reused
    static cudaStream_t s2 = nullptr;
    static cudaEvent_t ev1 = nullptr, ev2 = nullptr;
    if (!s2) {
        cudaStreamCreateWithFlags(&s2, cudaStreamNonBlocking);
        cudaEventCreateWithFlags(&ev1, cudaEventDisableTiming);
        cudaEventCreateWithFlags(&ev2, cudaEventDisableTiming);
    }

    const int TB = 256;
    int gemm_grid = (Nn + 63) / 64;
    int agg_grid = (Nn * 32 + TB - 1) / TB;

    // fork: CSR structure build on s2
    cudaEventRecord(ev1, 0);
    cudaStreamWaitEvent(s2, ev1, 0);
    cudaMemsetAsync(pdeg, 0, Nn * sizeof(int), s2);
    k_count<<<(Ee + TB - 1) / TB, TB, 0, s2>>>(el + Ee);
    k_scan1<<<NBLK, SCAN_B, 0, s2>>>();
    k_scan2<<<1, 64, 0, s2>>>();
    k_scan3<<<NBLK, SCAN_B, 0, s2>>>();
    k_fill<<<(Ee + TB - 1) / TB, TB, 0, s2>>>(el);
    cudaEventRecord(ev2, s2);

    // main stream: layer-0 GEMM (independent of structure)
    k_gemm64<<<gemm_grid, TB>>>(feats, W1, x, IND);

    // join: aggregation needs both CSR and x
    cudaStreamWaitEvent(0, ev2, 0);
    k_aggregate<<<agg_grid, TB>>>(x2, h2, (const float2*)b1, 0);

    // hidden layers
    for (int l = 0; l < Ll; l++) {
        k_gemm64<<<gemm_grid, TB>>>(h, W2 + (size_t)l * Hd * Hd, x, Hd);
        k_aggregate<<<agg_grid, TB>>>(x2, h2, (const float2*)(b2 + (size_t)l * Hd), 1);
    }

    // normalize + head + loss
    k_norm<<<agg_grid, TB>>>(h2, hout);
    k_head<<<(Nn + TB - 1) / TB, TB>>>(h, W3, b3, pred);
    k_loss<<<1, 1024>>>(pred, labels, tidx, out);
}

// round 16
// speedup vs baseline: 1.5409x; 1.5409x over previous
#include <cuda_runtime.h>
#include <math.h>

#define Nn 50000
#define Ee 1600000
#define IND 256
#define Hd 64
#define Cc 16
#define Ll 2
#define NTr 5000

#define SCAN_B 1024
#define NBLK ((Nn + SCAN_B - 1) / SCAN_B)   // 49

// ---------------- device scratch (no allocations allowed) ----------------
__device__ float g_x[Nn * Hd];
__device__ float g_h[Nn * Hd];
__device__ float g_dinv[Nn];
__device__ int   g_deg[Nn];
__device__ int   g_off[Nn + 1];
__device__ int   g_cur[Nn];
__device__ int   g_csrsrc[Ee];
__device__ int   g_bsum[NBLK];

// ---------------- degree / CSR build ----------------
__global__ void k_deg0() {
    int i = blockIdx.x * blockDim.x + threadIdx.x;
    if (i < Nn) g_deg[i] = 0;
}

__global__ void k_count(const int* __restrict__ dst) {
    int e = blockIdx.x * blockDim.x + threadIdx.x;
    if (e < Ee) atomicAdd(&g_deg[dst[e]], 1);
}

__global__ void k_scan1() {
    __shared__ int warpsums[32];
    int tid = threadIdx.x;
    int lane = tid & 31, wid = tid >> 5;
    int i = blockIdx.x * SCAN_B + tid;
    int v = (i < Nn) ? g_deg[i] : 0;
    if (i < Nn) g_dinv[i] = rsqrtf((float)v + 1.0f);   // +1 self loop

    int x = v;
#pragma unroll
    for (int d = 1; d < 32; d <<= 1) {
        int t = __shfl_up_sync(0xffffffffu, x, d);
        if (lane >= d) x += t;
    }
    if (lane == 31) warpsums[wid] = x;
    __syncthreads();
    if (wid == 0) {
        int w = warpsums[lane];
#pragma unroll
        for (int d = 1; d < 32; d <<= 1) {
            int t = __shfl_up_sync(0xffffffffu, w, d);
            if (lane >= d) w += t;
        }
        warpsums[lane] = w;
    }
    __syncthreads();
    int excl = x - v + (wid ? warpsums[wid - 1] : 0);
    if (i < Nn) g_off[i] = excl;
    if (tid == SCAN_B - 1) g_bsum[blockIdx.x] = excl + v;
}

__global__ void k_scan2() {
    __shared__ int s[64];
    int tid = threadIdx.x;    // blockDim = 64
    int v = (tid < NBLK) ? g_bsum[tid] : 0;
    s[tid] = v;
    __syncthreads();
#pragma unroll
    for (int d = 1; d < 64; d <<= 1) {
        int t = (tid >= d) ? s[tid - d] : 0;
        __syncthreads();
        s[tid] += t;
        __syncthreads();
    }
    if (tid < NBLK) g_bsum[tid] = s[tid] - v;
    if (tid == NBLK - 1) g_off[Nn] = s[tid];
}

__global__ void k_scan3() {
    int i = blockIdx.x * SCAN_B + threadIdx.x;
    if (i < Nn) {
        int o = g_off[i] + g_bsum[blockIdx.x];
        g_off[i] = o;
        g_cur[i] = o;
    }
}

__global__ void k_fill(const int* __restrict__ el) {
    int e = blockIdx.x * blockDim.x + threadIdx.x;
    if (e < Ee) {
        int s = el[e];
        int d = el[Ee + e];
        int p = atomicAdd(&g_cur[d], 1);
        g_csrsrc[p] = s;
    }
}

// ---------------- GEMM: A[N,K] @ W[K,64] -> Out[N,64] (proven version) ----------------
__global__ void k_gemm64(const float* __restrict__ A, const float* __restrict__ W,
                         float* __restrict__ Out, int K) {
    __shared__ float As[64 * 65];
    __shared__ float Ws[64 * 64];
    int tid = threadIdx.x;
    int rq = tid >> 4;
    int cq = tid & 15;
    int row0 = blockIdx.x * 64;
    float acc[4][4];
#pragma unroll
    for (int i = 0; i < 4; i++)
#pragma unroll
        for (int j = 0; j < 4; j++) acc[i][j] = 0.f;

    for (int kt = 0; kt < K; kt += 64) {
#pragma unroll
        for (int q = 0; q < 16; q++) {
            int pos = tid + 256 * q;
            int ar = pos >> 6, ac = pos & 63;
            int grow = row0 + ar;
            As[ar * 65 + ac] = (grow < Nn) ? A[(size_t)grow * K + kt + ac] : 0.f;
            Ws[pos] = W[(size_t)(kt + ar) * 64 + ac];
        }
        __syncthreads();
#pragma unroll
        for (int k = 0; k < 64; k++) {
            float a0 = As[(rq * 4 + 0) * 65 + k];
            float a1 = As[(rq * 4 + 1) * 65 + k];
            float a2 = As[(rq * 4 + 2) * 65 + k];
            float a3 = As[(rq * 4 + 3) * 65 + k];
            float4 w = *(const float4*)(&Ws[k * 64 + cq * 4]);
            acc[0][0] += a0 * w.x; acc[0][1] += a0 * w.y; acc[0][2] += a0 * w.z; acc[0][3] += a0 * w.w;
            acc[1][0] += a1 * w.x; acc[1][1] += a1 * w.y; acc[1][2] += a1 * w.z; acc[1][3] += a1 * w.w;
            acc[2][0] += a2 * w.x; acc[2][1] += a2 * w.y; acc[2][2] += a2 * w.z; acc[2][3] += a2 * w.w;
            acc[3][0] += a3 * w.x; acc[3][1] += a3 * w.y; acc[3][2] += a3 * w.z; acc[3][3] += a3 * w.w;
        }
        __syncthreads();
    }
#pragma unroll
    for (int i = 0; i < 4; i++) {
        int grow = row0 + rq * 4 + i;
        if (grow < Nn) {
            float4 v = make_float4(acc[i][0], acc[i][1], acc[i][2], acc[i][3]);
            *(float4*)(&Out[(size_t)grow * 64 + cq * 4]) = v;
        }
    }
}

// ---------------- aggregation (warp per node, scalar lanes, x8 unroll) ----------------
__global__ void k_aggregate(const float* __restrict__ x, float* __restrict__ out,
                            const float* __restrict__ bias, int dorelu) {
    int warp = (blockIdx.x * blockDim.x + threadIdx.x) >> 5;
    int lane = threadIdx.x & 31;
    if (warp >= Nn) return;
    float di = g_dinv[warp];
    float sn = di * di;
    float acc0 = sn * x[warp * 64 + lane];
    float acc1 = sn * x[warp * 64 + 32 + lane];
    int p = g_off[warp], end = g_off[warp + 1];

    for (; p + 8 <= end; p += 8) {
        int s0 = g_csrsrc[p + 0];
        int s1 = g_csrsrc[p + 1];
        int s2 = g_csrsrc[p + 2];
        int s3 = g_csrsrc[p + 3];
        int s4 = g_csrsrc[p + 4];
        int s5 = g_csrsrc[p + 5];
        int s6 = g_csrsrc[p + 6];
        int s7 = g_csrsrc[p + 7];
        float a0 = x[s0 * 64 + lane], b0 = x[s0 * 64 + 32 + lane];
        float a1 = x[s1 * 64 + lane], b1 = x[s1 * 64 + 32 + lane];
        float a2 = x[s2 * 64 + lane], b2 = x[s2 * 64 + 32 + lane];
        float a3 = x[s3 * 64 + lane], b3 = x[s3 * 64 + 32 + lane];
        float a4 = x[s4 * 64 + lane], b4 = x[s4 * 64 + 32 + lane];
        float a5 = x[s5 * 64 + lane], b5 = x[s5 * 64 + 32 + lane];
        float a6 = x[s6 * 64 + lane], b6 = x[s6 * 64 + 32 + lane];
        float a7 = x[s7 * 64 + lane], b7 = x[s7 * 64 + 32 + lane];
        float n0 = di * g_dinv[s0];
        float n1 = di * g_dinv[s1];
        float n2 = di * g_dinv[s2];
        float n3 = di * g_dinv[s3];
        float n4 = di * g_dinv[s4];
        float n5 = di * g_dinv[s5];
        float n6 = di * g_dinv[s6];
        float n7 = di * g_dinv[s7];
        acc0 += n0 * a0; acc1 += n0 * b0;
        acc0 += n1 * a1; acc1 += n1 * b1;
        acc0 += n2 * a2; acc1 += n2 * b2;
        acc0 += n3 * a3; acc1 += n3 * b3;
        acc0 += n4 * a4; acc1 += n4 * b4;
        acc0 += n5 * a5; acc1 += n5 * b5;
        acc0 += n6 * a6; acc1 += n6 * b6;
        acc0 += n7 * a7; acc1 += n7 * b7;
    }
    for (; p + 4 <= end; p += 4) {
        int s0 = g_csrsrc[p + 0];
        int s1 = g_csrsrc[p + 1];
        int s2 = g_csrsrc[p + 2];
        int s3 = g_csrsrc[p + 3];
        float n0 = di * g_dinv[s0];
        float n1 = di * g_dinv[s1];
        float n2 = di * g_dinv[s2];
        float n3 = di * g_dinv[s3];
        float a0 = x[s0 * 64 + lane], b0 = x[s0 * 64 + 32 + lane];
        float a1 = x[s1 * 64 + lane], b1 = x[s1 * 64 + 32 + lane];
        float a2 = x[s2 * 64 + lane], b2 = x[s2 * 64 + 32 + lane];
        float a3 = x[s3 * 64 + lane], b3 = x[s3 * 64 + 32 + lane];
        acc0 += n0 * a0; acc1 += n0 * b0;
        acc0 += n1 * a1; acc1 += n1 * b1;
        acc0 += n2 * a2; acc1 += n2 * b2;
        acc0 += n3 * a3; acc1 += n3 * b3;
    }
    for (; p < end; p++) {
        int s = g_csrsrc[p];
        float nrm = di * g_dinv[s];
        acc0 += nrm * x[s * 64 + lane];
        acc1 += nrm * x[s * 64 + 32 + lane];
    }
    acc0 += bias[lane];
    acc1 += bias[32 + lane];
    if (dorelu) { acc0 = fmaxf(acc0, 0.f); acc1 = fmaxf(acc1, 0.f); }
    out[warp * 64 + lane] = acc0;
    out[warp * 64 + 32 + lane] = acc1;
}

// ---------------- row L2 normalize (coalesced warp-per-node) ----------------
__global__ void k_norm(float* __restrict__ h, float* __restrict__ hout) {
    int warp = (blockIdx.x * blockDim.x + threadIdx.x) >> 5;
    int lane = threadIdx.x & 31;
    if (warp >= Nn) return;
    float a = h[warp * 64 + lane];
    float b = h[warp * 64 + 32 + lane];
    float ss = a * a + b * b;
#pragma unroll
    for (int d = 16; d; d >>= 1) ss += __shfl_xor_sync(0xffffffff, ss, d);
    float inv = 1.f / fmaxf(sqrtf(ss), 1e-12f);
    a *= inv; b *= inv;
    h[warp * 64 + lane] = a;
    h[warp * 64 + 32 + lane] = b;
    hout[warp * 64 + lane] = a;
    hout[warp * 64 + 32 + lane] = b;
}

// ---------------- head: logits = h@W3 + b3 ; log_softmax ----------------
__global__ void k_head(const float* __restrict__ h, const float* __restrict__ W3,
                       const float* __restrict__ b3, float* __restrict__ pred) {
    __shared__ float Ws[64 * 16];
    __shared__ float bs[16];
    int tid = threadIdx.x;
    for (int i = tid; i < 64 * 16; i += 256) Ws[i] = W3[i];
    if (tid < 16) bs[tid] = b3[tid];
    __syncthreads();
    int n = blockIdx.x * 256 + tid;
    if (n >= Nn) return;
    float hv[64];
#pragma unroll
    for (int q = 0; q < 16; q++) {
        float4 v = *(const float4*)(&h[(size_t)n * 64 + q * 4]);
        hv[q * 4 + 0] = v.x; hv[q * 4 + 1] = v.y; hv[q * 4 + 2] = v.z; hv[q * 4 + 3] = v.w;
    }
    float lg[16];
#pragma unroll
    for (int c = 0; c < 16; c++) {
        float acc = bs[c];
#pragma unroll
        for (int k = 0; k < 64; k++) acc += hv[k] * Ws[k * 16 + c];
        lg[c] = acc;
    }
    float m = lg[0];
#pragma unroll
    for (int c = 1; c < 16; c++) m = fmaxf(m, lg[c]);
    float s = 0.f;
#pragma unroll
    for (int c = 0; c < 16; c++) s += __expf(lg[c] - m);
    float lse = m + __logf(s);
#pragma unroll
    for (int c = 0; c < 16; c++) pred[(size_t)n * 16 + c] = lg[c] - lse;
}

// ---------------- nll loss ----------------
__global__ void k_loss(const float* __restrict__ pred, const int* __restrict__ labels,
                       const int* __restrict__ tidx, float* __restrict__ out0) {
    __shared__ float s[1024];
    int t = threadIdx.x;
    float local = 0.f;
    for (int i = t; i < NTr; i += 1024) {
        int n = tidx[i];
        int lbl = labels[n];
        local += pred[(size_t)n * 16 + lbl];
    }
    s[t] = local;
    __syncthreads();
    for (int d = 512; d > 0; d >>= 1) {
        if (t < d) s[t] += s[t + d];
        __syncthreads();
    }
    if (t == 0) out0[0] = -s[0] / (float)NTr;
}

// ---------------- launch: fork CSR build alongside GEMM1, join at aggregate ----------------
extern "C" void kernel_launch(void* const* d_in, const int* in_sizes, int n_in,
                              void* d_out, int out_size) {
    const float* feats  = (const float*)d_in[0];
    const float* W1     = (const float*)d_in[1];
    const float* b1     = (const float*)d_in[2];
    const float* W2     = (const float*)d_in[3];
    const float* b2     = (const float*)d_in[4];
    const float* W3     = (const float*)d_in[5];
    const float* b3     = (const float*)d_in[6];
    const int*   el     = (const int*)d_in[7];
    const int*   labels = (const int*)d_in[8];
    const int*   tidx   = (const int*)d_in[9];
    float* out  = (float*)d_out;
    float* pred = out + 1;
    float* hout = out + 1 + (size_t)Nn * Cc;

    void *px, *ph;
    cudaGetSymbolAddress(&px, g_x);
    cudaGetSymbolAddress(&ph, g_h);
    float* x = (float*)px;
    float* h = (float*)ph;

    // host-side stream/event objects, created once and reused
    static cudaStream_t s2 = nullptr;
    static cudaEvent_t ev1 = nullptr, ev2 = nullptr;
    if (!s2) {
        cudaStreamCreateWithFlags(&s2, cudaStreamNonBlocking);
        cudaEventCreateWithFlags(&ev1, cudaEventDisableTiming);
        cudaEventCreateWithFlags(&ev2, cudaEventDisableTiming);
    }

    const int TB = 256;
    int gemm_grid = (Nn + 63) / 64;
    int agg_grid = (Nn * 32 + TB - 1) / TB;

    // fork: CSR structure build on s2
    cudaEventRecord(ev1, 0);
    cudaStreamWaitEvent(s2, ev1, 0);
    k_deg0<<<(Nn + TB - 1) / TB, TB, 0, s2>>>();
    k_count<<<(Ee + TB - 1) / TB, TB, 0, s2>>>(el + Ee);
    k_scan1<<<NBLK, SCAN_B, 0, s2>>>();
    k_scan2<<<1, 64, 0, s2>>>();
    k_scan3<<<NBLK, SCAN_B, 0, s2>>>();
    k_fill<<<(Ee + TB - 1) / TB, TB, 0, s2>>>(el);
    cudaEventRecord(ev2, s2);

    // main stream: layer-0 GEMM (independent of structure)
    k_gemm64<<<gemm_grid, TB>>>(feats, W1, x, IND);

    // join: aggregation needs both CSR and x
    cudaStreamWaitEvent(0, ev2, 0);
    k_aggregate<<<agg_grid, TB>>>(x, h, b1, 0);

    // hidden layers
    for (int l = 0; l < Ll; l++) {
        k_gemm64<<<gemm_grid, TB>>>(h, W2 + (size_t)l * Hd * Hd, x, Hd);
        k_aggregate<<<agg_grid, TB>>>(x, h, b2 + (size_t)l * Hd, 1);
    }

    // normalize + head + loss
    k_norm<<<agg_grid, TB>>>(h, hout);
    k_head<<<(Nn + TB - 1) / TB, TB>>>(h, W3, b3, pred);
    k_loss<<<1, 1024>>>(pred, labels, tidx, out);
}